// round 5
// baseline (speedup 1.0000x reference)
#include <cuda_runtime.h>
#include <cuda_bf16.h>
#include <math.h>

#define NN   50000
#define FIN  128
#define HID  64
#define H1   4
#define NGR  512
#define EE   800000
#define ET   (EE + NN)        // 850000 edges incl. self loops
#define C1   (H1 * HID)       // 256 = layer-1 width

// ---------------- scratch (device globals; no allocation allowed) -----------
// zero-initialized-per-call region (one contiguous block, cleared by zero_kernel)
static const size_t OFF_SUM1 = 0;                                   // NN*4
static const size_t OFF_OUT1 = OFF_SUM1 + (size_t)NN * H1;          // NN*256
static const size_t OFF_SUM2 = OFF_OUT1 + (size_t)NN * C1;          // NN
static const size_t OFF_OUT2 = OFF_SUM2 + (size_t)NN;               // NN*64
static const size_t OFF_POOL = OFF_OUT2 + (size_t)NN * HID;         // NGR*64
static const size_t OFF_CNT  = OFF_POOL + (size_t)NGR * HID;        // NGR
static const size_t ZERO_TOT = OFF_CNT + (size_t)NGR;               // 16,283,280 floats

__device__ __align__(16) float g_zero[ZERO_TOT];
__device__ __align__(16) float g_h1[(size_t)NN * C1];     // x @ W1
__device__ __align__(16) float g_asrc1[(size_t)NN * H1];
__device__ __align__(16) float g_adst1[(size_t)NN * H1];
__device__ __align__(16) float g_p1[(size_t)ET * H1];     // exp(leaky(e)) per edge/head
__device__ __align__(16) float g_h2[(size_t)NN * HID];    // relu(out1+b1) @ W2
__device__ float g_asrc2[NN];
__device__ float g_adst2[NN];
__device__ __align__(16) float g_p2[ET];

// vectorized global reductions (sm_90+)
__device__ __forceinline__ void red4(float* p, float x, float y, float z, float w) {
    asm volatile("red.global.add.v4.f32 [%0], {%1, %2, %3, %4};"
                 :: "l"(p), "f"(x), "f"(y), "f"(z), "f"(w) : "memory");
}

__device__ __forceinline__ float lrelu(float v) { return v > 0.f ? v : 0.2f * v; }

// clamp to valid node range: garbage-proof against dtype surprises (diagnosable
// wrong-answer instead of illegal access)
__device__ __forceinline__ int clampn(int v, int hi) {
    return v < 0 ? 0 : (v >= hi ? hi - 1 : v);
}

// decode edge e -> (src, dst) from int32 edge_index, appending self-loops
__device__ __forceinline__ void edge_sd(const int* __restrict__ ei, int e, int& s, int& d) {
    if (e < EE) {
        s = clampn(ei[e], NN);
        d = clampn(ei[EE + e], NN);
    } else {
        s = d = e - EE;
    }
}

// ---------------- kernels ---------------------------------------------------

__global__ void zero_kernel() {
    size_t n4 = ZERO_TOT / 4;
    float4 z = make_float4(0.f, 0.f, 0.f, 0.f);
    for (size_t i = (size_t)blockIdx.x * blockDim.x + threadIdx.x; i < n4;
         i += (size_t)gridDim.x * blockDim.x)
        reinterpret_cast<float4*>(g_zero)[i] = z;
}

// C[M=NN, 256] = X[M,128] @ W1[128,256]
__global__ void gemm1_kernel(const float* __restrict__ X, const float* __restrict__ W) {
    __shared__ float As[16][128];
    __shared__ float Bs[16][128];
    const int bm = blockIdx.x * 128;
    const int bn = blockIdx.y * 128;
    const int tid = threadIdx.x;           // 256
    const int tx = tid & 15, ty = tid >> 4;
    float acc[8][8];
#pragma unroll
    for (int i = 0; i < 8; i++)
#pragma unroll
        for (int j = 0; j < 8; j++) acc[i][j] = 0.f;

    for (int k0 = 0; k0 < FIN; k0 += 16) {
#pragma unroll
        for (int i = 0; i < 2; i++) {              // A tile 128x16 (transposed store)
            int idx = tid + i * 256;               // 512 float4
            int row = idx >> 2;
            int kc  = (idx & 3) * 4;
            float4 v = make_float4(0.f, 0.f, 0.f, 0.f);
            int gr = bm + row;
            if (gr < NN) v = *reinterpret_cast<const float4*>(&X[(size_t)gr * FIN + k0 + kc]);
            As[kc + 0][row] = v.x; As[kc + 1][row] = v.y;
            As[kc + 2][row] = v.z; As[kc + 3][row] = v.w;
        }
#pragma unroll
        for (int i = 0; i < 2; i++) {              // B tile 16x128
            int idx = tid + i * 256;
            int kr = idx >> 5;
            int nc = (idx & 31) * 4;
            *reinterpret_cast<float4*>(&Bs[kr][nc]) =
                *reinterpret_cast<const float4*>(&W[(size_t)(k0 + kr) * C1 + bn + nc]);
        }
        __syncthreads();
#pragma unroll
        for (int kk = 0; kk < 16; kk++) {
            float a[8], b[8];
#pragma unroll
            for (int i = 0; i < 8; i++) a[i] = As[kk][ty * 8 + i];
#pragma unroll
            for (int j = 0; j < 8; j++) b[j] = Bs[kk][tx * 8 + j];
#pragma unroll
            for (int i = 0; i < 8; i++)
#pragma unroll
                for (int j = 0; j < 8; j++) acc[i][j] += a[i] * b[j];
        }
        __syncthreads();
    }
#pragma unroll
    for (int i = 0; i < 8; i++) {
        int gr = bm + ty * 8 + i;
        if (gr < NN) {
            float4* dst = reinterpret_cast<float4*>(&g_h1[(size_t)gr * C1 + bn + tx * 8]);
            dst[0] = make_float4(acc[i][0], acc[i][1], acc[i][2], acc[i][3]);
            dst[1] = make_float4(acc[i][4], acc[i][5], acc[i][6], acc[i][7]);
        }
    }
}

// asrc1/adst1[n,h] = dot(h1[n, h*64 : (h+1)*64], a_{src,dst}1[h])
__global__ void att1_kernel(const float* __restrict__ a_src, const float* __restrict__ a_dst) {
    __shared__ float sa[C1], sd[C1];
    int tid = threadIdx.x;
    sa[tid] = a_src[tid];
    sd[tid] = a_dst[tid];
    __syncthreads();
    int warp = tid >> 5, lane = tid & 31;
    int n = blockIdx.x * 8 + warp;
    if (n >= NN) return;
    const float* hr = &g_h1[(size_t)n * C1];
#pragma unroll
    for (int h = 0; h < H1; h++) {
        float x0 = hr[h * 64 + lane], x1 = hr[h * 64 + 32 + lane];
        float va = x0 * sa[h * 64 + lane] + x1 * sa[h * 64 + 32 + lane];
        float vd = x0 * sd[h * 64 + lane] + x1 * sd[h * 64 + 32 + lane];
#pragma unroll
        for (int off = 16; off > 0; off >>= 1) {
            va += __shfl_down_sync(0xffffffffu, va, off);
            vd += __shfl_down_sync(0xffffffffu, vd, off);
        }
        if (lane == 0) { g_asrc1[n * H1 + h] = va; g_adst1[n * H1 + h] = vd; }
    }
}

// per-edge: p = exp(leaky(asrc[src]+adst[dst])); sum1[dst] += p
__global__ void edgeA1_kernel(const int* __restrict__ ei) {
    int e = blockIdx.x * 256 + threadIdx.x;
    if (e >= ET) return;
    int s, d;
    edge_sd(ei, e, s, d);
    float4 as = *reinterpret_cast<const float4*>(&g_asrc1[(size_t)s * H1]);
    float4 ad = *reinterpret_cast<const float4*>(&g_adst1[(size_t)d * H1]);
    float4 p;
    p.x = expf(lrelu(as.x + ad.x));
    p.y = expf(lrelu(as.y + ad.y));
    p.z = expf(lrelu(as.z + ad.z));
    p.w = expf(lrelu(as.w + ad.w));
    *reinterpret_cast<float4*>(&g_p1[(size_t)e * H1]) = p;
    red4(&g_zero[OFF_SUM1 + (size_t)d * H1], p.x, p.y, p.z, p.w);
}

// warp per edge: out1[dst, h*64+k] += alpha * h1[src, h*64+k]
__global__ void edgeB1_kernel(const int* __restrict__ ei) {
    int tid = threadIdx.x;
    int e = blockIdx.x * 8 + (tid >> 5);
    if (e >= ET) return;
    int lane = tid & 31;
    int head = lane >> 3, part = lane & 7;
    int s, d;
    edge_sd(ei, e, s, d);
    float p  = g_p1[(size_t)e * H1 + head];
    float sm = g_zero[OFF_SUM1 + (size_t)d * H1 + head];
    float alpha = p / (sm + 1e-16f);
    const float4* hp =
        reinterpret_cast<const float4*>(&g_h1[(size_t)s * C1 + head * 64 + part * 8]);
    float4 v0 = hp[0], v1 = hp[1];
    float* ob = &g_zero[OFF_OUT1 + (size_t)d * C1 + head * 64 + part * 8];
    red4(ob,     alpha * v0.x, alpha * v0.y, alpha * v0.z, alpha * v0.w);
    red4(ob + 4, alpha * v1.x, alpha * v1.y, alpha * v1.z, alpha * v1.w);
}

// h2[M=NN, 64] = relu(out1 + b1)[M,256] @ W2[256,64]   (bias+relu fused into A load)
__global__ void gemm2_kernel(const float* __restrict__ W2, const float* __restrict__ b1) {
    __shared__ float As[16][128];
    __shared__ float Bs[16][64];
    const int bm = blockIdx.x * 128;
    const int tid = threadIdx.x;           // 256
    const int tx = tid & 15, ty = tid >> 4;
    float acc[8][4];
#pragma unroll
    for (int i = 0; i < 8; i++)
#pragma unroll
        for (int j = 0; j < 4; j++) acc[i][j] = 0.f;

    const float* A = &g_zero[OFF_OUT1];
    for (int k0 = 0; k0 < C1; k0 += 16) {
#pragma unroll
        for (int i = 0; i < 2; i++) {
            int idx = tid + i * 256;
            int row = idx >> 2;
            int kc  = (idx & 3) * 4;
            float4 v = make_float4(0.f, 0.f, 0.f, 0.f);
            int gr = bm + row;
            if (gr < NN) v = *reinterpret_cast<const float4*>(&A[(size_t)gr * C1 + k0 + kc]);
            As[kc + 0][row] = fmaxf(v.x + __ldg(&b1[k0 + kc + 0]), 0.f);
            As[kc + 1][row] = fmaxf(v.y + __ldg(&b1[k0 + kc + 1]), 0.f);
            As[kc + 2][row] = fmaxf(v.z + __ldg(&b1[k0 + kc + 2]), 0.f);
            As[kc + 3][row] = fmaxf(v.w + __ldg(&b1[k0 + kc + 3]), 0.f);
        }
        {   // B tile 16x64 = 256 float4, one per thread
            int kr = tid >> 4;
            int nc = (tid & 15) * 4;
            *reinterpret_cast<float4*>(&Bs[kr][nc]) =
                *reinterpret_cast<const float4*>(&W2[(size_t)(k0 + kr) * HID + nc]);
        }
        __syncthreads();
#pragma unroll
        for (int kk = 0; kk < 16; kk++) {
            float a[8], b[4];
#pragma unroll
            for (int i = 0; i < 8; i++) a[i] = As[kk][ty * 8 + i];
#pragma unroll
            for (int j = 0; j < 4; j++) b[j] = Bs[kk][tx * 4 + j];
#pragma unroll
            for (int i = 0; i < 8; i++)
#pragma unroll
                for (int j = 0; j < 4; j++) acc[i][j] += a[i] * b[j];
        }
        __syncthreads();
    }
#pragma unroll
    for (int i = 0; i < 8; i++) {
        int gr = bm + ty * 8 + i;
        if (gr < NN)
            *reinterpret_cast<float4*>(&g_h2[(size_t)gr * HID + tx * 4]) =
                make_float4(acc[i][0], acc[i][1], acc[i][2], acc[i][3]);
    }
}

__global__ void att2_kernel(const float* __restrict__ a_src, const float* __restrict__ a_dst) {
    __shared__ float sa[HID], sd[HID];
    int tid = threadIdx.x;
    if (tid < HID) { sa[tid] = a_src[tid]; sd[tid] = a_dst[tid]; }
    __syncthreads();
    int warp = tid >> 5, lane = tid & 31;
    int n = blockIdx.x * 8 + warp;
    if (n >= NN) return;
    float x0 = g_h2[(size_t)n * HID + lane], x1 = g_h2[(size_t)n * HID + 32 + lane];
    float va = x0 * sa[lane] + x1 * sa[32 + lane];
    float vd = x0 * sd[lane] + x1 * sd[32 + lane];
#pragma unroll
    for (int off = 16; off > 0; off >>= 1) {
        va += __shfl_down_sync(0xffffffffu, va, off);
        vd += __shfl_down_sync(0xffffffffu, vd, off);
    }
    if (lane == 0) { g_asrc2[n] = va; g_adst2[n] = vd; }
}

__global__ void edgeA2_kernel(const int* __restrict__ ei) {
    int e = blockIdx.x * 256 + threadIdx.x;
    if (e >= ET) return;
    int s, d;
    edge_sd(ei, e, s, d);
    float p = expf(lrelu(g_asrc2[s] + g_adst2[d]));
    g_p2[e] = p;
    atomicAdd(&g_zero[OFF_SUM2 + (size_t)d], p);
}

// 8 lanes per edge: out2[dst, k] += alpha * h2[src, k]
__global__ void edgeB2_kernel(const int* __restrict__ ei) {
    int tid = threadIdx.x;
    int idx = blockIdx.x * 256 + tid;
    int e = idx >> 3;
    if (e >= ET) return;
    int part = tid & 7;
    int s, d;
    edge_sd(ei, e, s, d);
    float alpha = g_p2[e] / (g_zero[OFF_SUM2 + (size_t)d] + 1e-16f);
    const float4* hp = reinterpret_cast<const float4*>(&g_h2[(size_t)s * HID + part * 8]);
    float4 v0 = hp[0], v1 = hp[1];
    float* ob = &g_zero[OFF_OUT2 + (size_t)d * HID + part * 8];
    red4(ob,     alpha * v0.x, alpha * v0.y, alpha * v0.z, alpha * v0.w);
    red4(ob + 4, alpha * v1.x, alpha * v1.y, alpha * v1.z, alpha * v1.w);
}

// relu(out2 + b2) -> segment (graph) sum + count
__global__ void pool_kernel(const int* __restrict__ batch, const float* __restrict__ b2) {
    int idx = blockIdx.x * 256 + threadIdx.x;
    if (idx >= NN * HID) return;
    int n = idx >> 6, j = idx & 63;
    int g = clampn(batch[n], NGR);
    float v = fmaxf(g_zero[OFF_OUT2 + (size_t)n * HID + j] + __ldg(&b2[j]), 0.f);
    atomicAdd(&g_zero[OFF_POOL + (size_t)g * HID + j], v);
    if (j == 0) atomicAdd(&g_zero[OFF_CNT + (size_t)g], 1.0f);
}

// mean pool -> logits -> log_softmax
__global__ void final_kernel(const float* __restrict__ Wc, const float* __restrict__ bc,
                             float* __restrict__ out) {
    int g = blockIdx.x, j = threadIdx.x;     // 64 threads
    float cnt = g_zero[OFF_CNT + (size_t)g];
    float m = g_zero[OFF_POOL + (size_t)g * HID + j] / fmaxf(cnt, 1.0f);
    __shared__ float s0[64], s1[64];
    s0[j] = m * Wc[j * 2 + 0];
    s1[j] = m * Wc[j * 2 + 1];
    __syncthreads();
    if (j == 0) {
        float l0 = bc[0], l1 = bc[1];
        for (int i = 0; i < 64; i++) { l0 += s0[i]; l1 += s1[i]; }
        float mx = fmaxf(l0, l1);
        float lse = mx + logf(expf(l0 - mx) + expf(l1 - mx));
        out[g * 2 + 0] = l0 - lse;
        out[g * 2 + 1] = l1 - lse;
    }
}

// ---------------- launch ----------------------------------------------------
extern "C" void kernel_launch(void* const* d_in, const int* in_sizes, int n_in,
                              void* d_out, int out_size) {
    const float* x      = (const float*)d_in[0];
    const int*   ei     = (const int*)d_in[1];     // int32 (JAX x64 disabled)
    const int*   batch  = (const int*)d_in[2];     // int32
    const float* W1     = (const float*)d_in[3];
    const float* a_src1 = (const float*)d_in[4];
    const float* a_dst1 = (const float*)d_in[5];
    const float* b1     = (const float*)d_in[6];
    const float* W2     = (const float*)d_in[7];
    const float* a_src2 = (const float*)d_in[8];
    const float* a_dst2 = (const float*)d_in[9];
    const float* b2     = (const float*)d_in[10];
    const float* Wc     = (const float*)d_in[11];
    const float* bc     = (const float*)d_in[12];
    float* out = (float*)d_out;

    zero_kernel<<<4096, 256>>>();
    gemm1_kernel<<<dim3((NN + 127) / 128, C1 / 128), 256>>>(x, W1);
    att1_kernel<<<(NN + 7) / 8, 256>>>(a_src1, a_dst1);
    edgeA1_kernel<<<(ET + 255) / 256, 256>>>(ei);
    edgeB1_kernel<<<(ET + 7) / 8, 256>>>(ei);
    gemm2_kernel<<<(NN + 127) / 128, 256>>>(W2, b1);
    att2_kernel<<<(NN + 7) / 8, 256>>>(a_src2, a_dst2);
    edgeA2_kernel<<<(ET + 255) / 256, 256>>>(ei);
    edgeB2_kernel<<<(ET * 8 + 255) / 256, 256>>>(ei);
    pool_kernel<<<(NN * HID + 255) / 256, 256>>>(batch, b2);
    final_kernel<<<NGR, HID>>>(Wc, bc, out);
}

// round 6
// speedup vs baseline: 1.4719x; 1.4719x over previous
#include <cuda_runtime.h>
#include <cuda_bf16.h>
#include <math.h>

#define NN   50000
#define FIN  128
#define HID  64
#define H1   4
#define NGR  512
#define EE   800000
#define ET   (EE + NN)        // 850000 edges incl. self loops
#define C1   (H1 * HID)       // 256 = layer-1 width

// ---------------- scratch (device globals; no allocation allowed) -----------
__device__ __align__(16) float g_h1[(size_t)NN * C1];     // x @ W1
__device__ __align__(16) float g_out1[(size_t)NN * C1];   // GAT1 aggregate
__device__ __align__(16) float g_h2[(size_t)NN * HID];    // relu(out1+b1) @ W2
__device__ __align__(16) float g_out2[(size_t)NN * HID];  // GAT2 aggregate
__device__ __align__(16) float g_asrc1[(size_t)NN * H1];
__device__ __align__(16) float g_adst1[(size_t)NN * H1];
__device__ float g_asrc2[NN];
__device__ float g_adst2[NN];
__device__ float g_pool[(size_t)NGR * HID];
__device__ float g_cnt[NGR];
// CSR by destination node
__device__ int g_deg[NN];
__device__ int g_wr[NN];
__device__ int g_rowptr[NN + 1];
__device__ int g_csr_src[ET];

__device__ __forceinline__ float lrelu(float v) { return v > 0.f ? v : 0.2f * v; }

__device__ __forceinline__ int clampn(int v, int hi) {
    return v < 0 ? 0 : (v >= hi ? hi - 1 : v);
}

// decode edge e -> (src, dst) from int32 edge_index, appending self-loops
__device__ __forceinline__ void edge_sd(const int* __restrict__ ei, int e, int& s, int& d) {
    if (e < EE) {
        s = clampn(ei[e], NN);
        d = clampn(ei[EE + e], NN);
    } else {
        s = d = e - EE;
    }
}

// ---------------- CSR build -------------------------------------------------

__global__ void zero_kernel() {
    int i = blockIdx.x * 256 + threadIdx.x;
    if (i < NN) { g_deg[i] = 0; g_wr[i] = 0; }
    if (i < NGR * HID) g_pool[i] = 0.f;
    if (i < NGR) g_cnt[i] = 0.f;
}

__global__ void deg_kernel(const int* __restrict__ ei) {
    int e = blockIdx.x * 256 + threadIdx.x;
    if (e >= ET) return;
    int d = (e < EE) ? clampn(ei[EE + e], NN) : e - EE;
    atomicAdd(&g_deg[d], 1);
}

// single-block exclusive scan of deg -> rowptr (shuffle-based, 1024 threads)
__global__ void scan_kernel() {
    __shared__ int wsum[32];
    __shared__ int carry_s;
    int tid = threadIdx.x, lane = tid & 31, w = tid >> 5;
    if (tid == 0) { carry_s = 0; g_rowptr[0] = 0; }
    __syncthreads();
    for (int base = 0; base < NN; base += 1024) {
        int i = base + tid;
        int x = (i < NN) ? g_deg[i] : 0;
#pragma unroll
        for (int off = 1; off < 32; off <<= 1) {
            int t = __shfl_up_sync(0xffffffffu, x, off);
            if (lane >= off) x += t;
        }
        if (lane == 31) wsum[w] = x;
        __syncthreads();
        if (w == 0) {
            int s = wsum[lane];
#pragma unroll
            for (int off = 1; off < 32; off <<= 1) {
                int t = __shfl_up_sync(0xffffffffu, s, off);
                if (lane >= off) s += t;
            }
            wsum[lane] = s;
        }
        __syncthreads();
        int incl = x + (w > 0 ? wsum[w - 1] : 0) + carry_s;
        if (i < NN) g_rowptr[i + 1] = incl;
        __syncthreads();
        if (tid == 1023) carry_s = incl;
        __syncthreads();
    }
}

__global__ void scatter_kernel(const int* __restrict__ ei) {
    int e = blockIdx.x * 256 + threadIdx.x;
    if (e >= ET) return;
    int s, d;
    edge_sd(ei, e, s, d);
    int pos = g_rowptr[d] + atomicAdd(&g_wr[d], 1);
    g_csr_src[pos] = s;
}

// ---------------- dense kernels ---------------------------------------------

// C[M=NN, 256] = X[M,128] @ W1[128,256]
__global__ void gemm1_kernel(const float* __restrict__ X, const float* __restrict__ W) {
    __shared__ float As[16][128];
    __shared__ float Bs[16][128];
    const int bm = blockIdx.x * 128;
    const int bn = blockIdx.y * 128;
    const int tid = threadIdx.x;           // 256
    const int tx = tid & 15, ty = tid >> 4;
    float acc[8][8];
#pragma unroll
    for (int i = 0; i < 8; i++)
#pragma unroll
        for (int j = 0; j < 8; j++) acc[i][j] = 0.f;

    for (int k0 = 0; k0 < FIN; k0 += 16) {
#pragma unroll
        for (int i = 0; i < 2; i++) {              // A tile 128x16 (transposed store)
            int idx = tid + i * 256;               // 512 float4
            int row = idx >> 2;
            int kc  = (idx & 3) * 4;
            float4 v = make_float4(0.f, 0.f, 0.f, 0.f);
            int gr = bm + row;
            if (gr < NN) v = *reinterpret_cast<const float4*>(&X[(size_t)gr * FIN + k0 + kc]);
            As[kc + 0][row] = v.x; As[kc + 1][row] = v.y;
            As[kc + 2][row] = v.z; As[kc + 3][row] = v.w;
        }
#pragma unroll
        for (int i = 0; i < 2; i++) {              // B tile 16x128
            int idx = tid + i * 256;
            int kr = idx >> 5;
            int nc = (idx & 31) * 4;
            *reinterpret_cast<float4*>(&Bs[kr][nc]) =
                *reinterpret_cast<const float4*>(&W[(size_t)(k0 + kr) * C1 + bn + nc]);
        }
        __syncthreads();
#pragma unroll
        for (int kk = 0; kk < 16; kk++) {
            float a[8], b[8];
#pragma unroll
            for (int i = 0; i < 8; i++) a[i] = As[kk][ty * 8 + i];
#pragma unroll
            for (int j = 0; j < 8; j++) b[j] = Bs[kk][tx * 8 + j];
#pragma unroll
            for (int i = 0; i < 8; i++)
#pragma unroll
                for (int j = 0; j < 8; j++) acc[i][j] += a[i] * b[j];
        }
        __syncthreads();
    }
#pragma unroll
    for (int i = 0; i < 8; i++) {
        int gr = bm + ty * 8 + i;
        if (gr < NN) {
            float4* dst = reinterpret_cast<float4*>(&g_h1[(size_t)gr * C1 + bn + tx * 8]);
            dst[0] = make_float4(acc[i][0], acc[i][1], acc[i][2], acc[i][3]);
            dst[1] = make_float4(acc[i][4], acc[i][5], acc[i][6], acc[i][7]);
        }
    }
}

// asrc1/adst1[n,h] = dot(h1[n, h*64 : (h+1)*64], a_{src,dst}1[h])
__global__ void att1_kernel(const float* __restrict__ a_src, const float* __restrict__ a_dst) {
    __shared__ float sa[C1], sd[C1];
    int tid = threadIdx.x;
    sa[tid] = a_src[tid];
    sd[tid] = a_dst[tid];
    __syncthreads();
    int warp = tid >> 5, lane = tid & 31;
    int n = blockIdx.x * 8 + warp;
    if (n >= NN) return;
    const float* hr = &g_h1[(size_t)n * C1];
#pragma unroll
    for (int h = 0; h < H1; h++) {
        float x0 = hr[h * 64 + lane], x1 = hr[h * 64 + 32 + lane];
        float va = x0 * sa[h * 64 + lane] + x1 * sa[h * 64 + 32 + lane];
        float vd = x0 * sd[h * 64 + lane] + x1 * sd[h * 64 + 32 + lane];
#pragma unroll
        for (int off = 16; off > 0; off >>= 1) {
            va += __shfl_down_sync(0xffffffffu, va, off);
            vd += __shfl_down_sync(0xffffffffu, vd, off);
        }
        if (lane == 0) { g_asrc1[n * H1 + h] = va; g_adst1[n * H1 + h] = vd; }
    }
}

// fused softmax + aggregate, layer 1: one warp per dst node.
// lane -> head = lane>>3, part = lane&7 (8 floats of that head's 64).
// Pass 1 computes the softmax denominator (8 lanes per head redundantly),
// pass 2 recomputes p and accumulates alpha * h1[src] in registers.
__global__ void gather1_kernel() {
    int warp = blockIdx.x * 8 + (threadIdx.x >> 5);
    if (warp >= NN) return;
    const int d = warp;
    const int lane = threadIdx.x & 31;
    const int head = lane >> 3, part = lane & 7;

    const int r0 = g_rowptr[d], r1 = g_rowptr[d + 1];
    const float adst = g_adst1[(size_t)d * H1 + head];

    float sum = 0.f;
    for (int j = r0; j < r1; j++) {
        int s = g_csr_src[j];
        sum += __expf(lrelu(g_asrc1[(size_t)s * H1 + head] + adst));
    }
    const float rs = 1.f / (sum + 1e-16f);

    float a0 = 0.f, a1 = 0.f, a2 = 0.f, a3 = 0.f, a4 = 0.f, a5 = 0.f, a6 = 0.f, a7 = 0.f;
    for (int j = r0; j < r1; j++) {
        int s = g_csr_src[j];
        float al = __expf(lrelu(g_asrc1[(size_t)s * H1 + head] + adst)) * rs;
        const float4* hp =
            reinterpret_cast<const float4*>(&g_h1[(size_t)s * C1 + head * 64 + part * 8]);
        float4 v0 = hp[0], v1 = hp[1];
        a0 += al * v0.x; a1 += al * v0.y; a2 += al * v0.z; a3 += al * v0.w;
        a4 += al * v1.x; a5 += al * v1.y; a6 += al * v1.z; a7 += al * v1.w;
    }
    float4* o = reinterpret_cast<float4*>(&g_out1[(size_t)d * C1 + head * 64 + part * 8]);
    o[0] = make_float4(a0, a1, a2, a3);
    o[1] = make_float4(a4, a5, a6, a7);
}

// h2[M=NN, 64] = relu(out1 + b1)[M,256] @ W2[256,64]   (bias+relu fused into A load)
__global__ void gemm2_kernel(const float* __restrict__ W2, const float* __restrict__ b1) {
    __shared__ float As[16][128];
    __shared__ float Bs[16][64];
    const int bm = blockIdx.x * 128;
    const int tid = threadIdx.x;           // 256
    const int tx = tid & 15, ty = tid >> 4;
    float acc[8][4];
#pragma unroll
    for (int i = 0; i < 8; i++)
#pragma unroll
        for (int j = 0; j < 4; j++) acc[i][j] = 0.f;

    const float* A = g_out1;
    for (int k0 = 0; k0 < C1; k0 += 16) {
#pragma unroll
        for (int i = 0; i < 2; i++) {
            int idx = tid + i * 256;
            int row = idx >> 2;
            int kc  = (idx & 3) * 4;
            float4 v = make_float4(0.f, 0.f, 0.f, 0.f);
            int gr = bm + row;
            if (gr < NN) v = *reinterpret_cast<const float4*>(&A[(size_t)gr * C1 + k0 + kc]);
            As[kc + 0][row] = fmaxf(v.x + __ldg(&b1[k0 + kc + 0]), 0.f);
            As[kc + 1][row] = fmaxf(v.y + __ldg(&b1[k0 + kc + 1]), 0.f);
            As[kc + 2][row] = fmaxf(v.z + __ldg(&b1[k0 + kc + 2]), 0.f);
            As[kc + 3][row] = fmaxf(v.w + __ldg(&b1[k0 + kc + 3]), 0.f);
        }
        {   // B tile 16x64 = 256 float4, one per thread
            int kr = tid >> 4;
            int nc = (tid & 15) * 4;
            *reinterpret_cast<float4*>(&Bs[kr][nc]) =
                *reinterpret_cast<const float4*>(&W2[(size_t)(k0 + kr) * HID + nc]);
        }
        __syncthreads();
#pragma unroll
        for (int kk = 0; kk < 16; kk++) {
            float a[8], b[4];
#pragma unroll
            for (int i = 0; i < 8; i++) a[i] = As[kk][ty * 8 + i];
#pragma unroll
            for (int j = 0; j < 4; j++) b[j] = Bs[kk][tx * 4 + j];
#pragma unroll
            for (int i = 0; i < 8; i++)
#pragma unroll
                for (int j = 0; j < 4; j++) acc[i][j] += a[i] * b[j];
        }
        __syncthreads();
    }
#pragma unroll
    for (int i = 0; i < 8; i++) {
        int gr = bm + ty * 8 + i;
        if (gr < NN)
            *reinterpret_cast<float4*>(&g_h2[(size_t)gr * HID + tx * 4]) =
                make_float4(acc[i][0], acc[i][1], acc[i][2], acc[i][3]);
    }
}

__global__ void att2_kernel(const float* __restrict__ a_src, const float* __restrict__ a_dst) {
    __shared__ float sa[HID], sd[HID];
    int tid = threadIdx.x;
    if (tid < HID) { sa[tid] = a_src[tid]; sd[tid] = a_dst[tid]; }
    __syncthreads();
    int warp = tid >> 5, lane = tid & 31;
    int n = blockIdx.x * 8 + warp;
    if (n >= NN) return;
    float x0 = g_h2[(size_t)n * HID + lane], x1 = g_h2[(size_t)n * HID + 32 + lane];
    float va = x0 * sa[lane] + x1 * sa[32 + lane];
    float vd = x0 * sd[lane] + x1 * sd[32 + lane];
#pragma unroll
    for (int off = 16; off > 0; off >>= 1) {
        va += __shfl_down_sync(0xffffffffu, va, off);
        vd += __shfl_down_sync(0xffffffffu, vd, off);
    }
    if (lane == 0) { g_asrc2[n] = va; g_adst2[n] = vd; }
}

// fused softmax + aggregate, layer 2: one warp per dst, lane -> 2 floats of 64
__global__ void gather2_kernel() {
    int warp = blockIdx.x * 8 + (threadIdx.x >> 5);
    if (warp >= NN) return;
    const int d = warp;
    const int lane = threadIdx.x & 31;

    const int r0 = g_rowptr[d], r1 = g_rowptr[d + 1];
    const float adst = g_adst2[d];

    float sum = 0.f;
    for (int j = r0; j < r1; j++) {
        int s = g_csr_src[j];
        sum += __expf(lrelu(g_asrc2[s] + adst));
    }
    const float rs = 1.f / (sum + 1e-16f);

    float a0 = 0.f, a1 = 0.f;
    for (int j = r0; j < r1; j++) {
        int s = g_csr_src[j];
        float al = __expf(lrelu(g_asrc2[s] + adst)) * rs;
        float2 v = *reinterpret_cast<const float2*>(&g_h2[(size_t)s * HID + lane * 2]);
        a0 += al * v.x; a1 += al * v.y;
    }
    *reinterpret_cast<float2*>(&g_out2[(size_t)d * HID + lane * 2]) = make_float2(a0, a1);
}

// relu(out2 + b2) -> segment (graph) sum + count
__global__ void pool_kernel(const int* __restrict__ batch, const float* __restrict__ b2) {
    int idx = blockIdx.x * 256 + threadIdx.x;
    if (idx >= NN * HID) return;
    int n = idx >> 6, j = idx & 63;
    int g = clampn(batch[n], NGR);
    float v = fmaxf(g_out2[(size_t)n * HID + j] + __ldg(&b2[j]), 0.f);
    atomicAdd(&g_pool[(size_t)g * HID + j], v);
    if (j == 0) atomicAdd(&g_cnt[g], 1.0f);
}

// mean pool -> logits -> log_softmax
__global__ void final_kernel(const float* __restrict__ Wc, const float* __restrict__ bc,
                             float* __restrict__ out) {
    int g = blockIdx.x, j = threadIdx.x;     // 64 threads
    float cnt = g_cnt[g];
    float m = g_pool[(size_t)g * HID + j] / fmaxf(cnt, 1.0f);
    __shared__ float s0[64], s1[64];
    s0[j] = m * Wc[j * 2 + 0];
    s1[j] = m * Wc[j * 2 + 1];
    __syncthreads();
    if (j == 0) {
        float l0 = bc[0], l1 = bc[1];
        for (int i = 0; i < 64; i++) { l0 += s0[i]; l1 += s1[i]; }
        float mx = fmaxf(l0, l1);
        float lse = mx + logf(expf(l0 - mx) + expf(l1 - mx));
        out[g * 2 + 0] = l0 - lse;
        out[g * 2 + 1] = l1 - lse;
    }
}

// ---------------- launch ----------------------------------------------------
extern "C" void kernel_launch(void* const* d_in, const int* in_sizes, int n_in,
                              void* d_out, int out_size) {
    const float* x      = (const float*)d_in[0];
    const int*   ei     = (const int*)d_in[1];     // int32 (JAX x64 disabled)
    const int*   batch  = (const int*)d_in[2];     // int32
    const float* W1     = (const float*)d_in[3];
    const float* a_src1 = (const float*)d_in[4];
    const float* a_dst1 = (const float*)d_in[5];
    const float* b1     = (const float*)d_in[6];
    const float* W2     = (const float*)d_in[7];
    const float* a_src2 = (const float*)d_in[8];
    const float* a_dst2 = (const float*)d_in[9];
    const float* b2     = (const float*)d_in[10];
    const float* Wc     = (const float*)d_in[11];
    const float* bc     = (const float*)d_in[12];
    float* out = (float*)d_out;

    zero_kernel<<<(NN + 255) / 256, 256>>>();
    deg_kernel<<<(ET + 255) / 256, 256>>>(ei);
    scan_kernel<<<1, 1024>>>();
    scatter_kernel<<<(ET + 255) / 256, 256>>>(ei);
    gemm1_kernel<<<dim3((NN + 127) / 128, C1 / 128), 256>>>(x, W1);
    att1_kernel<<<(NN + 7) / 8, 256>>>(a_src1, a_dst1);
    gather1_kernel<<<(NN + 7) / 8, 256>>>();
    gemm2_kernel<<<(NN + 127) / 128, 256>>>(W2, b1);
    att2_kernel<<<(NN + 7) / 8, 256>>>(a_src2, a_dst2);
    gather2_kernel<<<(NN + 7) / 8, 256>>>();
    pool_kernel<<<(NN * HID + 255) / 256, 256>>>(batch, b2);
    final_kernel<<<NGR, HID>>>(Wc, bc, out);
}